// round 10
// baseline (speedup 1.0000x reference)
#include <cuda_runtime.h>
#include <cuda_bf16.h>
#include <cstdint>

// Implicit-GEMM 3x3 conv via warp-level bf16 mma.sync, fp32 via hi/lo split:
//   D += Ah*Bh + Ah*Bl + Al*Bh  (fp32 accumulators)
// R10: CTA tile 128x256 (grid.y=1), 8 warps of 64x64 -> LDSM bytes per MMA
// halved (85B/MMA); B staged via cp.async (pre-split planar bf16 weights).

#define CONV_HW  56
#define CONV_PIX 3136
#define CONV_K   256
#define GEMM_K   2304
#define X_ELEMS  (32 * 256 * CONV_PIX)
#define W_ELEMS  (CONV_K * GEMM_K)
#define BK       32
#define NCHUNK   (GEMM_K / BK)             // 72

#define PITCH    40                        // bf16 per smem row (80B), LDSM conflict-free
#define ROWB     (PITCH * 2)
#define A_ROWS   128
#define B_ROWS   256
#define A_BYTES  (A_ROWS * ROWB)           // 10240
#define B_BYTES  (B_ROWS * ROWB)           // 20480
#define OFF_AL   A_BYTES                   // 10240
#define OFF_BH   (2 * A_BYTES)             // 20480
#define OFF_BL   (2 * A_BYTES + B_BYTES)   // 40960
#define STAGE    (2 * A_BYTES + 2 * B_BYTES)  // 61440
#define SMEM_TOTAL (2 * STAGE)             // 122880

__device__ uint32_t      g_xs[X_ELEMS];    // hi | lo<<16
__device__ __nv_bfloat16 g_wh[W_ELEMS];
__device__ __nv_bfloat16 g_wl[W_ELEMS];

__device__ __forceinline__ uint32_t smem_u32(const void* p) {
    uint32_t a;
    asm("{ .reg .u64 t; cvta.to.shared.u64 t, %1; cvt.u32.u64 %0, t; }" : "=r"(a) : "l"(p));
    return a;
}
__device__ __forceinline__ uint32_t prmt(uint32_t a, uint32_t b, uint32_t sel) {
    uint32_t r;
    asm("prmt.b32 %0, %1, %2, %3;" : "=r"(r) : "r"(a), "r"(b), "r"(sel));
    return r;
}
__device__ __forceinline__ void cp_async16(uint32_t dst, const void* src) {
    asm volatile("cp.async.ca.shared.global [%0], [%1], 16;" :: "r"(dst), "l"(src));
}
#define CP_COMMIT() asm volatile("cp.async.commit_group;" ::: "memory")
#define CP_WAIT0()  asm volatile("cp.async.wait_group 0;" ::: "memory")

#define LDSM_X4(r0, r1, r2, r3, a) \
    asm volatile("ldmatrix.sync.aligned.m8n8.x4.shared.b16 {%0,%1,%2,%3}, [%4];" \
                 : "=r"(r0), "=r"(r1), "=r"(r2), "=r"(r3) : "r"(a))

#define MMA16816(c, a, b) \
    asm volatile("mma.sync.aligned.m16n8k16.row.col.f32.bf16.bf16.f32 " \
                 "{%0,%1,%2,%3}, {%4,%5,%6,%7}, {%8,%9}, {%0,%1,%2,%3};" \
                 : "+f"((c)[0]), "+f"((c)[1]), "+f"((c)[2]), "+f"((c)[3]) \
                 : "r"((a)[0]), "r"((a)[1]), "r"((a)[2]), "r"((a)[3]), \
                   "r"((b)[0]), "r"((b)[1]))

// ---------------- prep kernels ----------------

__global__ void split_x_kernel(const float* __restrict__ x) {
    const int i4 = blockIdx.x * blockDim.x + threadIdx.x;
    if (i4 * 4 >= X_ELEMS) return;
    const float4 v = *(const float4*)(x + (size_t)i4 * 4);
    const float vv[4] = {v.x, v.y, v.z, v.w};
    uint32_t r[4];
    #pragma unroll
    for (int j = 0; j < 4; j++) {
        __nv_bfloat16 h = __float2bfloat16(vv[j]);
        __nv_bfloat16 l = __float2bfloat16(vv[j] - __bfloat162float(h));
        r[j] = (uint32_t)*reinterpret_cast<uint16_t*>(&h)
             | ((uint32_t)*reinterpret_cast<uint16_t*>(&l) << 16);
    }
    *(uint4*)(g_xs + (size_t)i4 * 4) = make_uint4(r[0], r[1], r[2], r[3]);
}

__global__ void split_w_kernel(const float* __restrict__ w) {
    const int i = blockIdx.x * blockDim.x + threadIdx.x;
    if (i >= W_ELEMS) return;
    const float v = w[i];
    __nv_bfloat16 h = __float2bfloat16(v);
    __nv_bfloat16 l = __float2bfloat16(v - __bfloat162float(h));
    g_wh[i] = h;
    g_wl[i] = l;
}

// ---------------- main kernel ----------------

__global__ __launch_bounds__(256, 1)
void conv3x3_hmma_kernel(float* __restrict__ out) {
    extern __shared__ char smem[];
    const uint32_t sbase = smem_u32(smem);
    const int tid  = threadIdx.x;
    const int wrp  = tid >> 5;
    const int lane = tid & 31;

    const int block_m = blockIdx.x * 128;   // grid.y == 1: CTA covers all 256 oc

    // ---- A staging: m = tid&127, kg = (tid>>7)*16  (128 rows x 32 k)
    const int a_m  = tid & 127;
    const int a_kg = (tid >> 7) * 16;
    const int p_a    = block_m + a_m;
    const int nimg_a = p_a / CONV_PIX;
    const int hw_a   = p_a - nimg_a * CONV_PIX;
    const int oh     = hw_a / CONV_HW;
    const int ow     = hw_a - oh * CONV_HW;
    const uint32_t* xs_n = g_xs + (size_t)nimg_a * CONV_K * CONV_PIX;

    // ---- B staging via cp.async: row = tid (256 oc), 64B (32 bf16) per chunk
    const __nv_bfloat16* whp = g_wh + (size_t)tid * GEMM_K;
    const __nv_bfloat16* wlp = g_wl + (size_t)tid * GEMM_K;
    const uint32_t b_sts = (uint32_t)tid * ROWB;

    // ---- warp tile 64x64: warp_m = wrp&1, warp_n = wrp>>1
    const int m0 = (wrp & 1) * 64;
    const int n0 = (wrp >> 1) * 64;

    const uint32_t a_lm_off = (uint32_t)(m0 + (lane & 15)) * ROWB + (uint32_t)(lane >> 4) * 16;
    const uint32_t b_lm_off = (uint32_t)(n0 + (lane & 7) + ((lane >> 4) << 3)) * ROWB
                            + (uint32_t)((lane >> 3) & 1) * 16;

    float acc[4][8][4];
    #pragma unroll
    for (int i = 0; i < 4; i++)
        #pragma unroll
        for (int j = 0; j < 8; j++)
            #pragma unroll
            for (int r = 0; r < 4; r++) acc[i][j][r] = 0.f;

    uint32_t axv[16];

    auto load_A = [&](int kt) {
        int k0 = kt + a_kg;
        int c  = k0 / 9;
        int rs = k0 - c * 9;
        int r  = rs / 3;
        int s  = rs - r * 3;
        const uint32_t* xc = xs_n + c * CONV_PIX;
        #pragma unroll
        for (int j = 0; j < 16; j++) {
            const int ih = oh + r - 1, iw = ow + s - 1;
            const bool ok = ((unsigned)ih < CONV_HW) && ((unsigned)iw < CONV_HW);
            axv[j] = ok ? __ldg(xc + ih * CONV_HW + iw) : 0u;
            if (++s == 3) { s = 0; if (++r == 3) { r = 0; xc += CONV_PIX; } }
        }
    };
    auto store_A = [&](char* st) {
        char* Ah = st;
        char* Al = st + OFF_AL;
        #pragma unroll
        for (int t = 0; t < 4; t++) {   // pairs of k-pairs -> STS.64
            const uint32_t off = (uint32_t)a_m * ROWB + (uint32_t)(a_kg + 4 * t) * 2;
            uint32_t h0 = prmt(axv[4*t+0], axv[4*t+1], 0x5410);
            uint32_t h1 = prmt(axv[4*t+2], axv[4*t+3], 0x5410);
            uint32_t l0 = prmt(axv[4*t+0], axv[4*t+1], 0x7632);
            uint32_t l1 = prmt(axv[4*t+2], axv[4*t+3], 0x7632);
            *(uint2*)(Ah + off) = make_uint2(h0, h1);
            *(uint2*)(Al + off) = make_uint2(l0, l1);
        }
    };
    auto issue_B = [&](uint32_t sstage, int kt) {
        #pragma unroll
        for (int q = 0; q < 4; q++) {
            cp_async16(sstage + OFF_BH + b_sts + q * 16, whp + kt + q * 8);
            cp_async16(sstage + OFF_BL + b_sts + q * 16, wlp + kt + q * 8);
        }
        CP_COMMIT();
    };

    auto ldA = [&](uint32_t sstage, uint32_t base, uint32_t kso, int mt, uint32_t (&a)[4]) {
        LDSM_X4(a[0], a[1], a[2], a[3],
                sstage + base + a_lm_off + kso + (uint32_t)mt * 16 * ROWB);
    };
    auto ldB4 = [&](uint32_t sstage, uint32_t base, uint32_t kso, uint32_t (&b)[4][4]) {
        #pragma unroll
        for (int t = 0; t < 4; t++)
            LDSM_X4(b[t][0], b[t][1], b[t][2], b[t][3],
                    sstage + base + b_lm_off + kso + (uint32_t)t * 16 * ROWB);
    };

    // prologue: stage chunk 0
    issue_B(sbase, 0);
    load_A(0);
    store_A(smem);
    CP_WAIT0();
    __syncthreads();

    for (int c = 0; c < NCHUNK; ++c) {
        const int buf = c & 1;
        const uint32_t sstage = sbase + (uint32_t)buf * STAGE;
        const bool more = (c + 1) < NCHUNK;

        if (more) {
            issue_B(sbase + (uint32_t)(buf ^ 1) * STAGE, (c + 1) * BK);
            load_A((c + 1) * BK);
        }

        #pragma unroll
        for (int ks = 0; ks < 2; ks++) {
            const uint32_t kso = (uint32_t)ks * 32;
            uint32_t bh[4][4], bl[4][4];
            ldB4(sstage, OFF_BH, kso, bh);
            ldB4(sstage, OFF_BL, kso, bl);

            uint32_t aH[2][4], aL[2][4];
            ldA(sstage, 0,      kso, 0, aH[0]);
            ldA(sstage, OFF_AL, kso, 0, aL[0]);
            #pragma unroll
            for (int mt = 0; mt < 4; mt++) {
                const int cur = mt & 1;
                if (mt < 3) {                          // prefetch next m-frags
                    ldA(sstage, 0,      kso, mt + 1, aH[cur ^ 1]);
                    ldA(sstage, OFF_AL, kso, mt + 1, aL[cur ^ 1]);
                }
                #pragma unroll
                for (int nt = 0; nt < 8; nt++)
                    MMA16816(acc[mt][nt], aH[cur], &bh[nt >> 1][(nt & 1) * 2]);
                #pragma unroll
                for (int nt = 0; nt < 8; nt++)
                    MMA16816(acc[mt][nt], aH[cur], &bl[nt >> 1][(nt & 1) * 2]);
                #pragma unroll
                for (int nt = 0; nt < 8; nt++)
                    MMA16816(acc[mt][nt], aL[cur], &bh[nt >> 1][(nt & 1) * 2]);
            }
        }

        if (more) store_A(smem + (buf ^ 1) * STAGE);
        CP_WAIT0();
        __syncthreads();
    }

    // ---- epilogue: 128 floats per thread
    const int oc_base0 = n0 + (lane & 3) * 2;
    #pragma unroll
    for (int mt = 0; mt < 4; mt++) {
        const int p_lo = block_m + m0 + mt * 16 + (lane >> 2);
        const int p_hi = p_lo + 8;
        const int nl = p_lo / CONV_PIX, hl = p_lo - nl * CONV_PIX;
        const int nh = p_hi / CONV_PIX, hh = p_hi - nh * CONV_PIX;
        float* olo = out + (size_t)nl * CONV_K * CONV_PIX + hl;
        float* ohi = out + (size_t)nh * CONV_K * CONV_PIX + hh;
        #pragma unroll
        for (int nt = 0; nt < 8; nt++) {
            const int oc = oc_base0 + nt * 8;
            olo[(size_t)(oc    ) * CONV_PIX] = acc[mt][nt][0];
            olo[(size_t)(oc + 1) * CONV_PIX] = acc[mt][nt][1];
            ohi[(size_t)(oc    ) * CONV_PIX] = acc[mt][nt][2];
            ohi[(size_t)(oc + 1) * CONV_PIX] = acc[mt][nt][3];
        }
    }
}

extern "C" void kernel_launch(void* const* d_in, const int* in_sizes, int n_in,
                              void* d_out, int out_size) {
    const float* x = (const float*)d_in[0];
    const float* w = (const float*)d_in[1];
    float* out = (float*)d_out;

    split_x_kernel<<<(X_ELEMS / 4 + 255) / 256, 256>>>(x);
    split_w_kernel<<<(W_ELEMS + 255) / 256, 256>>>(w);

    cudaFuncSetAttribute(conv3x3_hmma_kernel,
                         cudaFuncAttributeMaxDynamicSharedMemorySize, SMEM_TOTAL);
    dim3 grid(784, 1);   // 128-pixel M tiles; CTA covers all 256 oc
    conv3x3_hmma_kernel<<<grid, 256, SMEM_TOTAL>>>(out);
}

// round 11
// speedup vs baseline: 1.2282x; 1.2282x over previous
#include <cuda_runtime.h>
#include <cuda_bf16.h>
#include <cstdint>

// Implicit-GEMM 3x3 conv via warp-level bf16 mma.sync, fp32 via hi/lo split:
//   D += Ah*Bh + Ah*Bl + Al*Bh  (fp32 accumulators)
// R11: CTA 128x256 (grid.y=1), 512 threads, 16 warps of 32x64.
// Liveness-ordered passes keep regs <= ~124 (no spills): Bh reused, then
// overwritten by Bl; A staging 8 elems/thread, stored early; B via cp.async.

#define CONV_HW  56
#define CONV_PIX 3136
#define CONV_K   256
#define GEMM_K   2304
#define X_ELEMS  (32 * 256 * CONV_PIX)
#define W_ELEMS  (CONV_K * GEMM_K)
#define BK       32
#define NCHUNK   (GEMM_K / BK)             // 72

#define PITCH    40                        // bf16 per smem row (80B), LDSM conflict-free
#define ROWB     (PITCH * 2)
#define A_BYTES  (128 * ROWB)              // 10240
#define B_BYTES  (256 * ROWB)              // 20480
#define OFF_AL   A_BYTES                   // 10240
#define OFF_BH   (2 * A_BYTES)             // 20480
#define OFF_BL   (2 * A_BYTES + B_BYTES)   // 40960
#define STAGE    (2 * A_BYTES + 2 * B_BYTES)  // 61440
#define SMEM_TOTAL (2 * STAGE)             // 122880

__device__ uint32_t      g_xs[X_ELEMS];    // hi | lo<<16
__device__ __nv_bfloat16 g_wh[W_ELEMS];
__device__ __nv_bfloat16 g_wl[W_ELEMS];

__device__ __forceinline__ uint32_t smem_u32(const void* p) {
    uint32_t a;
    asm("{ .reg .u64 t; cvta.to.shared.u64 t, %1; cvt.u32.u64 %0, t; }" : "=r"(a) : "l"(p));
    return a;
}
__device__ __forceinline__ uint32_t prmt(uint32_t a, uint32_t b, uint32_t sel) {
    uint32_t r;
    asm("prmt.b32 %0, %1, %2, %3;" : "=r"(r) : "r"(a), "r"(b), "r"(sel));
    return r;
}
__device__ __forceinline__ void cp_async16(uint32_t dst, const void* src) {
    asm volatile("cp.async.ca.shared.global [%0], [%1], 16;" :: "r"(dst), "l"(src));
}
#define CP_COMMIT() asm volatile("cp.async.commit_group;" ::: "memory")
#define CP_WAIT0()  asm volatile("cp.async.wait_group 0;" ::: "memory")

#define LDSM_X4(r0, r1, r2, r3, a) \
    asm volatile("ldmatrix.sync.aligned.m8n8.x4.shared.b16 {%0,%1,%2,%3}, [%4];" \
                 : "=r"(r0), "=r"(r1), "=r"(r2), "=r"(r3) : "r"(a))

#define MMA16816(c, a, b) \
    asm volatile("mma.sync.aligned.m16n8k16.row.col.f32.bf16.bf16.f32 " \
                 "{%0,%1,%2,%3}, {%4,%5,%6,%7}, {%8,%9}, {%0,%1,%2,%3};" \
                 : "+f"((c)[0]), "+f"((c)[1]), "+f"((c)[2]), "+f"((c)[3]) \
                 : "r"((a)[0]), "r"((a)[1]), "r"((a)[2]), "r"((a)[3]), \
                   "r"((b)[0]), "r"((b)[1]))

// ---------------- prep kernels ----------------

__global__ void split_x_kernel(const float* __restrict__ x) {
    const int i4 = blockIdx.x * blockDim.x + threadIdx.x;
    if (i4 * 4 >= X_ELEMS) return;
    const float4 v = *(const float4*)(x + (size_t)i4 * 4);
    const float vv[4] = {v.x, v.y, v.z, v.w};
    uint32_t r[4];
    #pragma unroll
    for (int j = 0; j < 4; j++) {
        __nv_bfloat16 h = __float2bfloat16(vv[j]);
        __nv_bfloat16 l = __float2bfloat16(vv[j] - __bfloat162float(h));
        r[j] = (uint32_t)*reinterpret_cast<uint16_t*>(&h)
             | ((uint32_t)*reinterpret_cast<uint16_t*>(&l) << 16);
    }
    *(uint4*)(g_xs + (size_t)i4 * 4) = make_uint4(r[0], r[1], r[2], r[3]);
}

__global__ void split_w_kernel(const float* __restrict__ w) {
    const int i = blockIdx.x * blockDim.x + threadIdx.x;
    if (i >= W_ELEMS) return;
    const float v = w[i];
    __nv_bfloat16 h = __float2bfloat16(v);
    __nv_bfloat16 l = __float2bfloat16(v - __bfloat162float(h));
    g_wh[i] = h;
    g_wl[i] = l;
}

// ---------------- main kernel ----------------

__global__ __launch_bounds__(512, 1)
void conv3x3_hmma_kernel(float* __restrict__ out) {
    extern __shared__ char smem[];
    const uint32_t sbase = smem_u32(smem);
    const int tid  = threadIdx.x;
    const int wrp  = tid >> 5;
    const int lane = tid & 31;

    const int block_m = blockIdx.x * 128;   // grid.y == 1: CTA covers all 256 oc

    // ---- A staging: m = tid&127, kg = (tid>>7)*8  (8 elems/thread)
    const int a_m  = tid & 127;
    const int a_kg = (tid >> 7) * 8;
    const int p_a    = block_m + a_m;
    const int nimg_a = p_a / CONV_PIX;
    const int hw_a   = p_a - nimg_a * CONV_PIX;
    const int oh     = hw_a / CONV_HW;
    const int ow     = hw_a - oh * CONV_HW;
    const uint32_t* xs_n = g_xs + (size_t)nimg_a * CONV_K * CONV_PIX;

    // ---- B staging via cp.async: row = tid>>1, quads q0 = (tid&1)*2 (+0,+1)
    const int b_row = tid >> 1;
    const int b_q0  = (tid & 1) * 2;
    const __nv_bfloat16* whp = g_wh + (size_t)b_row * GEMM_K + b_q0 * 8;
    const __nv_bfloat16* wlp = g_wl + (size_t)b_row * GEMM_K + b_q0 * 8;
    const uint32_t b_sts = (uint32_t)b_row * ROWB + (uint32_t)b_q0 * 16;

    // ---- warp tile 32x64: warp_m = wrp&3 (4x32 rows), warp_n = wrp>>2 (4x64 oc)
    const int m0 = (wrp & 3) * 32;
    const int n0 = (wrp >> 2) * 64;

    const uint32_t a_lm_off = (uint32_t)(m0 + (lane & 15)) * ROWB + (uint32_t)(lane >> 4) * 16;
    const uint32_t b_lm_off = (uint32_t)(n0 + (lane & 7) + ((lane >> 4) << 3)) * ROWB
                            + (uint32_t)((lane >> 3) & 1) * 16;

    float acc[2][8][4];
    #pragma unroll
    for (int i = 0; i < 2; i++)
        #pragma unroll
        for (int j = 0; j < 8; j++)
            #pragma unroll
            for (int r = 0; r < 4; r++) acc[i][j][r] = 0.f;

    uint32_t axv[8];

    auto load_A = [&](int kt) {
        int k0 = kt + a_kg;
        int c  = k0 / 9;
        int rs = k0 - c * 9;
        int r  = rs / 3;
        int s  = rs - r * 3;
        const uint32_t* xc = xs_n + c * CONV_PIX;
        #pragma unroll
        for (int j = 0; j < 8; j++) {
            const int ih = oh + r - 1, iw = ow + s - 1;
            const bool ok = ((unsigned)ih < CONV_HW) && ((unsigned)iw < CONV_HW);
            axv[j] = ok ? __ldg(xc + ih * CONV_HW + iw) : 0u;
            if (++s == 3) { s = 0; if (++r == 3) { r = 0; xc += CONV_PIX; } }
        }
    };
    auto store_A = [&](char* st) {
        char* Ah = st;
        char* Al = st + OFF_AL;
        #pragma unroll
        for (int t = 0; t < 2; t++) {
            const uint32_t off = (uint32_t)a_m * ROWB + (uint32_t)(a_kg + 4 * t) * 2;
            uint32_t h0 = prmt(axv[4*t+0], axv[4*t+1], 0x5410);
            uint32_t h1 = prmt(axv[4*t+2], axv[4*t+3], 0x5410);
            uint32_t l0 = prmt(axv[4*t+0], axv[4*t+1], 0x7632);
            uint32_t l1 = prmt(axv[4*t+2], axv[4*t+3], 0x7632);
            *(uint2*)(Ah + off) = make_uint2(h0, h1);
            *(uint2*)(Al + off) = make_uint2(l0, l1);
        }
    };
    auto issue_B = [&](uint32_t sstage, int kt) {
        #pragma unroll
        for (int q = 0; q < 2; q++) {
            cp_async16(sstage + OFF_BH + b_sts + q * 16, whp + kt + q * 8);
            cp_async16(sstage + OFF_BL + b_sts + q * 16, wlp + kt + q * 8);
        }
        CP_COMMIT();
    };

    auto ldA2 = [&](uint32_t sstage, uint32_t base, uint32_t kso, uint32_t (&a)[2][4]) {
        #pragma unroll
        for (int mt = 0; mt < 2; mt++)
            LDSM_X4(a[mt][0], a[mt][1], a[mt][2], a[mt][3],
                    sstage + base + a_lm_off + kso + (uint32_t)mt * 16 * ROWB);
    };
    auto ldB4 = [&](uint32_t sstage, uint32_t base, uint32_t kso, uint32_t (&b)[4][4]) {
        #pragma unroll
        for (int t = 0; t < 4; t++)
            LDSM_X4(b[t][0], b[t][1], b[t][2], b[t][3],
                    sstage + base + b_lm_off + kso + (uint32_t)t * 16 * ROWB);
    };
    auto mma_pass = [&](uint32_t (&a)[2][4], uint32_t (&b)[4][4]) {
        #pragma unroll
        for (int mt = 0; mt < 2; mt++)
            #pragma unroll
            for (int nt = 0; nt < 8; nt++)
                MMA16816(acc[mt][nt], a[mt], &b[nt >> 1][(nt & 1) * 2]);
    };

    // prologue: stage chunk 0 into buffer 0
    issue_B(sbase, 0);
    load_A(0);
    store_A(smem);
    CP_WAIT0();
    __syncthreads();

    for (int c = 0; c < NCHUNK; ++c) {
        const int buf = c & 1;
        const uint32_t sstage = sbase + (uint32_t)buf * STAGE;
        const bool more = (c + 1) < NCHUNK;

        if (more) {
            issue_B(sbase + (uint32_t)(buf ^ 1) * STAGE, (c + 1) * BK);
            load_A((c + 1) * BK);          // LDG latency hidden under compute
        }

        #pragma unroll
        for (int ks = 0; ks < 2; ks++) {
            const uint32_t kso = (uint32_t)ks * 32;
            uint32_t a_h[2][4], a_l[2][4], b[4][4];

            ldB4(sstage, OFF_BH, kso, b);      // Bh
            ldA2(sstage, 0,      kso, a_h);
            mma_pass(a_h, b);                  // Ah*Bh
            ldA2(sstage, OFF_AL, kso, a_l);
            mma_pass(a_l, b);                  // Al*Bh   (b dies here)
            ldB4(sstage, OFF_BL, kso, b);      // Bl overwrites
            if (ks == 0 && more) store_A(smem + (buf ^ 1) * STAGE);  // axv dies
            mma_pass(a_h, b);                  // Ah*Bl
        }

        CP_WAIT0();
        __syncthreads();
    }

    // ---- epilogue: 64 floats per thread
    const int oc_base = n0 + (lane & 3) * 2;
    #pragma unroll
    for (int mt = 0; mt < 2; mt++) {
        const int p_lo = block_m + m0 + mt * 16 + (lane >> 2);
        const int p_hi = p_lo + 8;
        const int nl = p_lo / CONV_PIX, hl = p_lo - nl * CONV_PIX;
        const int nh = p_hi / CONV_PIX, hh = p_hi - nh * CONV_PIX;
        float* olo = out + (size_t)nl * CONV_K * CONV_PIX + hl;
        float* ohi = out + (size_t)nh * CONV_K * CONV_PIX + hh;
        #pragma unroll
        for (int nt = 0; nt < 8; nt++) {
            const int oc = oc_base + nt * 8;
            olo[(size_t)(oc    ) * CONV_PIX] = acc[mt][nt][0];
            olo[(size_t)(oc + 1) * CONV_PIX] = acc[mt][nt][1];
            ohi[(size_t)(oc    ) * CONV_PIX] = acc[mt][nt][2];
            ohi[(size_t)(oc + 1) * CONV_PIX] = acc[mt][nt][3];
        }
    }
}

extern "C" void kernel_launch(void* const* d_in, const int* in_sizes, int n_in,
                              void* d_out, int out_size) {
    const float* x = (const float*)d_in[0];
    const float* w = (const float*)d_in[1];
    float* out = (float*)d_out;

    split_x_kernel<<<(X_ELEMS / 4 + 255) / 256, 256>>>(x);
    split_w_kernel<<<(W_ELEMS + 255) / 256, 256>>>(w);

    cudaFuncSetAttribute(conv3x3_hmma_kernel,
                         cudaFuncAttributeMaxDynamicSharedMemorySize, SMEM_TOTAL);
    dim3 grid(784, 1);   // 128-pixel M tiles; CTA covers all 256 oc
    conv3x3_hmma_kernel<<<grid, 512, SMEM_TOTAL>>>(out);
}